// round 12
// baseline (speedup 1.0000x reference)
#include <cuda_runtime.h>
#include <cstdint>

#define NN 50000
#define EE 400000
#define DD 128
#define HH 4
#define DHh 32
#define TT 3
#define RR 6
#define LLn 2
#define EPSV 1e-5f

// edge kernel: 8 warps/block, warp = 16 edges x 1 head, block = 32 edges
#define EDGE_GRID (EE / 32)

// ---------------- static scratch (no allocations allowed) ----------------
__device__ float g_k[NN * DD];
__device__ float g_q[NN * DD];
__device__ float g_v[NN * DD];
__device__ float g_agg[NN * DD];
__device__ float g_ha[NN * DD];
__device__ float g_o0[NN * DD];
__device__ float g_o1[NN * DD];
__device__ float g_den[NN * HH];

__device__ __forceinline__ uint32_t to_tf32(float v) {
    uint32_t r;
    asm("cvt.rna.tf32.f32 %0, %1;" : "=r"(r) : "f"(v));
    return r;
}

__device__ __forceinline__ void mma_tf32(float* c, uint32_t a0, uint32_t a1,
                                         uint32_t a2, uint32_t a3,
                                         uint32_t b0, uint32_t b1) {
    asm volatile(
        "mma.sync.aligned.m16n8k8.row.col.f32.tf32.tf32.f32 "
        "{%0,%1,%2,%3}, {%4,%5,%6,%7}, {%8,%9}, {%0,%1,%2,%3};"
        : "+f"(c[0]), "+f"(c[1]), "+f"(c[2]), "+f"(c[3])
        : "r"(a0), "r"(a1), "r"(a2), "r"(a3), "r"(b0), "r"(b1));
}

// ---------------- init: zero g_agg + g_den ----------------
__global__ void __launch_bounds__(256) init_kernel() {
    int i = blockIdx.x * blockDim.x + threadIdx.x;
    if (i < NN * DD / 4)
        ((float4*)g_agg)[i] = make_float4(0.f, 0.f, 0.f, 0.f);
    if (i < NN * HH)
        g_den[i] = 0.f;
}

// ---------------- tf32 tensor-core typed linear ------
#define XP 132
__global__ void __launch_bounds__(256) typed_linear_kernel(
    const float* __restrict__ xext, int in_sel,
    const int* __restrict__ ntype,
    const float* __restrict__ W0, const float* __restrict__ W1,
    const float* __restrict__ W2, int nmat)
{
    const float* x = (in_sel == 0) ? xext : (in_sel == 1 ? (const float*)g_agg
                                                         : (const float*)g_o0);
    __shared__ float xs[64][XP];
    __shared__ int ts[64];
    int tid = threadIdx.x;
    int row0 = blockIdx.x * 64;

    for (int i = tid; i < 64 * 32; i += 256) {
        int r = i >> 5, c4 = i & 31;
        int gr = row0 + r;
        float4 val = make_float4(0.f, 0.f, 0.f, 0.f);
        if (gr < NN) {
            val = ((const float4*)(x + (size_t)gr * DD))[c4];
            if (in_sel == 1) {
                float den = g_den[(size_t)gr * HH + (c4 >> 3)];
                float inv = (den > 0.f) ? (1.f / den) : 0.f;
                val.x *= inv; val.y *= inv; val.z *= inv; val.w *= inv;
            }
        }
        float4 t;
        t.x = __uint_as_float(to_tf32(val.x));
        t.y = __uint_as_float(to_tf32(val.y));
        t.z = __uint_as_float(to_tf32(val.z));
        t.w = __uint_as_float(to_tf32(val.w));
        *(float4*)&xs[r][c4 * 4] = t;
    }
    if (tid < 64) {
        int gr = row0 + tid;
        ts[tid] = ntype[gr < NN ? gr : NN - 1];
    }
    __syncthreads();

    const float* Wmat[3] = {W0, W1, W2};
    float* Omat[3] = {(nmat == 1) ? g_ha : g_k, g_q, g_v};
    bool homog = (ts[0] == ts[63]);

    int warp = tid >> 5, lane = tid & 31;
    int g = lane >> 2, tg = lane & 3;
    int wm = warp & 3, wn = warp >> 2;
    int m0 = wm * 16;

    if (homog) {
        for (int m = 0; m < nmat; ++m) {
            const float* Wt = Wmat[m] + (size_t)ts[0] * DD * DD;
            float acc[8][4];
#pragma unroll
            for (int a = 0; a < 8; a++)
                acc[a][0] = acc[a][1] = acc[a][2] = acc[a][3] = 0.f;

#pragma unroll
            for (int s = 0; s < 16; ++s) {
                int k0 = s * 8;
                uint32_t a0 = __float_as_uint(xs[m0 + g][k0 + tg]);
                uint32_t a1 = __float_as_uint(xs[m0 + g + 8][k0 + tg]);
                uint32_t a2 = __float_as_uint(xs[m0 + g][k0 + tg + 4]);
                uint32_t a3 = __float_as_uint(xs[m0 + g + 8][k0 + tg + 4]);
                const float* pb0 = Wt + (size_t)(k0 + tg) * DD + wn * 64 + g;
                const float* pb1 = Wt + (size_t)(k0 + tg + 4) * DD + wn * 64 + g;
                uint32_t b0[8], b1[8];
#pragma unroll
                for (int nc = 0; nc < 8; ++nc) {
                    b0[nc] = __float_as_uint(__ldg(pb0 + nc * 8));
                    b1[nc] = __float_as_uint(__ldg(pb1 + nc * 8));
                }
#pragma unroll
                for (int nc = 0; nc < 8; ++nc)
                    mma_tf32(acc[nc], a0, a1, a2, a3, b0[nc], b1[nc]);
            }
            float* out = Omat[m];
            int r1 = row0 + m0 + g, r2 = r1 + 8;
#pragma unroll
            for (int nc = 0; nc < 8; ++nc) {
                int col = wn * 64 + nc * 8 + 2 * tg;
                if (r1 < NN)
                    *(float2*)&out[(size_t)r1 * DD + col] = make_float2(acc[nc][0], acc[nc][1]);
                if (r2 < NN)
                    *(float2*)&out[(size_t)r2 * DD + col] = make_float2(acc[nc][2], acc[nc][3]);
            }
        }
    } else {
        for (int m = 0; m < nmat; ++m) {
            int cx = tid & 31, ry = tid >> 5;
            float acc[8][4];
#pragma unroll
            for (int a = 0; a < 8; a++)
                acc[a][0] = acc[a][1] = acc[a][2] = acc[a][3] = 0.f;
            for (int rr = 0; rr < 8; ++rr) {
                int r = ry * 8 + rr;
                const float* Wt = Wmat[m] + (size_t)ts[r] * DD * DD;
                for (int d = 0; d < DD; ++d) {
                    float xv = xs[r][d];
                    float4 w4 = __ldg((const float4*)(Wt + (size_t)d * DD + cx * 4));
                    acc[rr][0] += xv * w4.x; acc[rr][1] += xv * w4.y;
                    acc[rr][2] += xv * w4.z; acc[rr][3] += xv * w4.w;
                }
            }
            float* out = Omat[m];
#pragma unroll
            for (int rr = 0; rr < 8; ++rr) {
                int gr = row0 + ry * 8 + rr;
                if (gr < NN)
                    ((float4*)(out + (size_t)gr * DD))[cx] =
                        make_float4(acc[rr][0], acc[rr][1], acc[rr][2], acc[rr][3]);
            }
        }
    }
}

// ---------------- tensor-core fused edge kernel ----------------
// Warp = 16 edges x 1 head (hh = warp&3, edge-group = blockIdx*2 + warp>>2).
// Phase 1: kw = k_slice @ Wa[et] via tf32 mma; score = kw . q[dst]; exp; den.
// Phase 2: mv = v_slice @ Wm[et] via mma; scale by ex; red.v4 scatter.
__global__ void __launch_bounds__(256) edge_fused_kernel(
    const int* __restrict__ src, const int* __restrict__ dst,
    const int* __restrict__ etype,
    const float* __restrict__ Wa_, const float* __restrict__ Wm_,
    const float* __restrict__ pri)
{
    __shared__ float Asm[8][16][36];   // per-warp 16x32 tile (pad 36)
    const unsigned full = 0xffffffffu;
    int w = threadIdx.x >> 5, lane = threadIdx.x & 31;
    int hh = w & 3;
    int e0 = (blockIdx.x * 2 + (w >> 2)) * 16;
    int s_ = 0, d_ = 0, t_ = 0;
    if (lane < 16) { s_ = src[e0 + lane]; d_ = dst[e0 + lane]; t_ = etype[e0 + lane]; }
    int g = lane >> 2, tg = lane & 3;
    int et0 = __shfl_sync(full, t_, 0);
    int et15 = __shfl_sync(full, t_, 15);
    bool homog = (et0 == et15);
    int grow = lane >> 1, gf = (lane & 1) * 4;   // gather coords: row, f4 offset

    // ---- gather k head-slices into Asm (tf32-converted) ----
    {
        int sr = __shfl_sync(full, s_, grow);
        const float4* kp = (const float4*)(g_k + (size_t)sr * DD + hh * DHh);
#pragma unroll
        for (int i = 0; i < 4; ++i) {
            float4 kv = __ldg(kp + gf + i);
            float4 t;
            t.x = __uint_as_float(to_tf32(kv.x));
            t.y = __uint_as_float(to_tf32(kv.y));
            t.z = __uint_as_float(to_tf32(kv.z));
            t.w = __uint_as_float(to_tf32(kv.w));
            *(float4*)&Asm[w][grow][(gf + i) * 4] = t;
        }
    }
    __syncwarp();

    float exlo = 0.f, exhi = 0.f;     // homog path
    float exbuf[16];                  // fallback path
    int dlo = __shfl_sync(full, d_, g);
    int dhi = __shfl_sync(full, d_, g + 8);

    if (homog) {
        // ---- phase 1: kw = A @ Wa ----
        const float* WB = Wa_ + ((size_t)(hh * RR + et0)) * DHh * DHh;
        float acc[4][4];
#pragma unroll
        for (int a = 0; a < 4; a++) acc[a][0] = acc[a][1] = acc[a][2] = acc[a][3] = 0.f;
#pragma unroll
        for (int ks = 0; ks < 4; ++ks) {
            int k0 = ks * 8;
            uint32_t a0 = __float_as_uint(Asm[w][g][k0 + tg]);
            uint32_t a1 = __float_as_uint(Asm[w][g + 8][k0 + tg]);
            uint32_t a2 = __float_as_uint(Asm[w][g][k0 + tg + 4]);
            uint32_t a3 = __float_as_uint(Asm[w][g + 8][k0 + tg + 4]);
            const float* pb0 = WB + (k0 + tg) * DHh + g;
            const float* pb1 = WB + (k0 + tg + 4) * DHh + g;
#pragma unroll
            for (int nc = 0; nc < 4; ++nc) {
                uint32_t b0 = __float_as_uint(__ldg(pb0 + nc * 8));
                uint32_t b1 = __float_as_uint(__ldg(pb1 + nc * 8));
                mma_tf32(acc[nc], a0, a1, a2, a3, b0, b1);
            }
        }
        // ---- score = kw . q[dst], butterfly over tg ----
        float plo = 0.f, phi = 0.f;
#pragma unroll
        for (int nc = 0; nc < 4; ++nc) {
            int col = hh * DHh + nc * 8 + 2 * tg;
            float2 qlo = *(const float2*)(g_q + (size_t)dlo * DD + col);
            float2 qhi = *(const float2*)(g_q + (size_t)dhi * DD + col);
            plo += acc[nc][0] * qlo.x + acc[nc][1] * qlo.y;
            phi += acc[nc][2] * qhi.x + acc[nc][3] * qhi.y;
        }
        plo += __shfl_xor_sync(full, plo, 1);
        plo += __shfl_xor_sync(full, plo, 2);
        phi += __shfl_xor_sync(full, phi, 1);
        phi += __shfl_xor_sync(full, phi, 2);
        float pr = __ldg(pri + hh * RR + et0) * 0.17677669529663687f;
        exlo = expf(plo * pr);
        exhi = expf(phi * pr);
        if (tg == 0) {
            atomicAdd(g_den + (size_t)dlo * HH + hh, exlo);
            atomicAdd(g_den + (size_t)dhi * HH + hh, exhi);
        }
    } else {
        // ---- fallback: scalar per-edge (rare relation-boundary warps) ----
#pragma unroll 1
        for (int e = 0; e < 16; ++e) {
            int et = __shfl_sync(full, t_, e);
            int dE = __shfl_sync(full, d_, e);
            const float* WB = Wa_ + ((size_t)(hh * RR + et)) * DHh * DHh;
            float kw = 0.f;
            for (int d = 0; d < DHh; ++d)
                kw += Asm[w][e][d] * __ldg(WB + d * DHh + lane);
            float p = kw * __ldg(g_q + (size_t)dE * DD + hh * DHh + lane);
#pragma unroll
            for (int o = 16; o > 0; o >>= 1) p += __shfl_xor_sync(full, p, o);
            float ex = expf(p * __ldg(pri + hh * RR + et) * 0.17677669529663687f);
            exbuf[e] = ex;
            if (lane == 0) atomicAdd(g_den + (size_t)dE * HH + hh, ex);
        }
    }
    __syncwarp();

    // ---- gather v head-slices (overwrite Asm) ----
    {
        int sr = __shfl_sync(full, s_, grow);
        const float4* vp = (const float4*)(g_v + (size_t)sr * DD + hh * DHh);
#pragma unroll
        for (int i = 0; i < 4; ++i) {
            float4 vv = __ldg(vp + gf + i);
            float4 t;
            t.x = __uint_as_float(to_tf32(vv.x));
            t.y = __uint_as_float(to_tf32(vv.y));
            t.z = __uint_as_float(to_tf32(vv.z));
            t.w = __uint_as_float(to_tf32(vv.w));
            *(float4*)&Asm[w][grow][(gf + i) * 4] = t;
        }
    }
    __syncwarp();

    if (homog) {
        // ---- phase 2: mv = A @ Wm ----
        const float* WB = Wm_ + ((size_t)(hh * RR + et0)) * DHh * DHh;
        float acc[4][4];
#pragma unroll
        for (int a = 0; a < 4; a++) acc[a][0] = acc[a][1] = acc[a][2] = acc[a][3] = 0.f;
#pragma unroll
        for (int ks = 0; ks < 4; ++ks) {
            int k0 = ks * 8;
            uint32_t a0 = __float_as_uint(Asm[w][g][k0 + tg]);
            uint32_t a1 = __float_as_uint(Asm[w][g + 8][k0 + tg]);
            uint32_t a2 = __float_as_uint(Asm[w][g][k0 + tg + 4]);
            uint32_t a3 = __float_as_uint(Asm[w][g + 8][k0 + tg + 4]);
            const float* pb0 = WB + (k0 + tg) * DHh + g;
            const float* pb1 = WB + (k0 + tg + 4) * DHh + g;
#pragma unroll
            for (int nc = 0; nc < 4; ++nc) {
                uint32_t b0 = __float_as_uint(__ldg(pb0 + nc * 8));
                uint32_t b1 = __float_as_uint(__ldg(pb1 + nc * 8));
                mma_tf32(acc[nc], a0, a1, a2, a3, b0, b1);
            }
        }
        __syncwarp();   // all A reads done before overwrite with scaled messages
        // stage scaled messages into Asm
#pragma unroll
        for (int nc = 0; nc < 4; ++nc) {
            int col = nc * 8 + 2 * tg;
            *(float2*)&Asm[w][g][col] = make_float2(acc[nc][0] * exlo, acc[nc][1] * exlo);
            *(float2*)&Asm[w][g + 8][col] = make_float2(acc[nc][2] * exhi, acc[nc][3] * exhi);
        }
        __syncwarp();
        // cooperative red.v4 scatter: lane covers 16 floats of one edge-row
        int dr = __shfl_sync(full, d_, grow);
        float* base = g_agg + (size_t)dr * DD + hh * DHh;
#pragma unroll
        for (int i = 0; i < 4; ++i) {
            float4 mv = *(float4*)&Asm[w][grow][(gf + i) * 4];
            asm volatile("red.global.add.v4.f32 [%0], {%1,%2,%3,%4};"
                         :: "l"(base + (gf + i) * 4),
                            "f"(mv.x), "f"(mv.y), "f"(mv.z), "f"(mv.w)
                         : "memory");
        }
    } else {
#pragma unroll 1
        for (int e = 0; e < 16; ++e) {
            int et = __shfl_sync(full, t_, e);
            int dE = __shfl_sync(full, d_, e);
            const float* WB = Wm_ + ((size_t)(hh * RR + et)) * DHh * DHh;
            float mv = 0.f;
            for (int d = 0; d < DHh; ++d)
                mv += Asm[w][e][d] * __ldg(WB + d * DHh + lane);
            atomicAdd(g_agg + (size_t)dE * DD + hh * DHh + lane, mv * exbuf[e]);
        }
    }
}

// ---------------- skip gate + residual + layernorm ----------------
__global__ void fuse_ln_kernel(const float* __restrict__ xext, int in_sel,
                               const int* __restrict__ ntype,
                               const float* __restrict__ skp, const float* __restrict__ gg,
                               const float* __restrict__ bb, int out_sel)
{
    const float* xin = (in_sel == 0) ? xext : (const float*)g_o0;
    float* xout = (out_sel == 0) ? g_o0 : g_o1;
    int node = (blockIdx.x * blockDim.x + threadIdx.x) >> 5;
    int lane = threadIdx.x & 31;
    if (node >= NN) return;
    float4 x4 = ((const float4*)(xin + (size_t)node * DD))[lane];
    float4 a4 = ((const float4*)(g_ha + (size_t)node * DD))[lane];
    float sk = 1.f / (1.f + expf(-__ldg(skp + ntype[node])));
    float c = 2.f - sk;
    float4 z = make_float4(x4.x * c + a4.x * sk, x4.y * c + a4.y * sk,
                           x4.z * c + a4.z * sk, x4.w * c + a4.w * sk);
    float s = z.x + z.y + z.z + z.w;
#pragma unroll
    for (int o = 16; o > 0; o >>= 1) s += __shfl_xor_sync(0xffffffffu, s, o);
    float mu = s * (1.0f / DD);
    float dx = z.x - mu, dy = z.y - mu, dz = z.z - mu, dw = z.w - mu;
    float vs = dx * dx + dy * dy + dz * dz + dw * dw;
#pragma unroll
    for (int o = 16; o > 0; o >>= 1) vs += __shfl_xor_sync(0xffffffffu, vs, o);
    float inv = rsqrtf(vs * (1.0f / DD) + EPSV);
    float4 g4 = ((const float4*)gg)[lane];
    float4 b4 = ((const float4*)bb)[lane];
    ((float4*)(xout + (size_t)node * DD))[lane] =
        make_float4(dx * inv * g4.x + b4.x, dy * inv * g4.y + b4.y,
                    dz * inv * g4.z + b4.z, dw * inv * g4.w + b4.w);
}

// ---------------- layer aggregation + final layernorm ----------------
__global__ void final_kernel(const float* __restrict__ aw, const float* __restrict__ gg,
                             const float* __restrict__ bb, float* __restrict__ out)
{
    int node = (blockIdx.x * blockDim.x + threadIdx.x) >> 5;
    int lane = threadIdx.x & 31;
    if (node >= NN) return;
    float a0 = __ldg(aw), a1 = __ldg(aw + 1);
    float mw = fmaxf(a0, a1);
    float e0 = expf(a0 - mw), e1 = expf(a1 - mw);
    float den = e0 + e1;
    float w0 = e0 / den, w1 = e1 / den;
    float4 x0 = ((const float4*)(g_o0 + (size_t)node * DD))[lane];
    float4 x1 = ((const float4*)(g_o1 + (size_t)node * DD))[lane];
    float4 z = make_float4(w0 * x0.x + w1 * x1.x, w0 * x0.y + w1 * x1.y,
                           w0 * x0.z + w1 * x1.z, w0 * x0.w + w1 * x1.w);
    float s = z.x + z.y + z.z + z.w;
#pragma unroll
    for (int o = 16; o > 0; o >>= 1) s += __shfl_xor_sync(0xffffffffu, s, o);
    float mu = s * (1.0f / DD);
    float dx = z.x - mu, dy = z.y - mu, dz = z.z - mu, dw = z.w - mu;
    float vs = dx * dx + dy * dy + dz * dz + dw * dw;
#pragma unroll
    for (int o = 16; o > 0; o >>= 1) vs += __shfl_xor_sync(0xffffffffu, vs, o);
    float inv = rsqrtf(vs * (1.0f / DD) + EPSV);
    float4 g4 = ((const float4*)gg)[lane];
    float4 b4 = ((const float4*)bb)[lane];
    ((float4*)(out + (size_t)node * DD))[lane] =
        make_float4(dx * inv * g4.x + b4.x, dy * inv * g4.y + b4.y,
                    dz * inv * g4.z + b4.z, dw * inv * g4.w + b4.w);
}

// ---------------- launch ----------------
extern "C" void kernel_launch(void* const* d_in, const int* in_sizes, int n_in,
                              void* d_out, int out_size)
{
    (void)in_sizes; (void)n_in; (void)out_size;
    const float* h    = (const float*)d_in[0];
    const int*   src  = (const int*)d_in[1];
    const int*   dst  = (const int*)d_in[2];
    const int*   ntyp = (const int*)d_in[3];
    const int*   etyp = (const int*)d_in[4];
    const float* Wk   = (const float*)d_in[5];
    const float* Wq   = (const float*)d_in[6];
    const float* Wv   = (const float*)d_in[7];
    const float* Wa   = (const float*)d_in[8];
    const float* Watt = (const float*)d_in[9];
    const float* Wmsg = (const float*)d_in[10];
    const float* pri  = (const float*)d_in[11];
    const float* skip = (const float*)d_in[12];
    const float* lng  = (const float*)d_in[13];
    const float* lnb  = (const float*)d_in[14];
    const float* aggw = (const float*)d_in[15];
    const float* aggg = (const float*)d_in[16];
    const float* aggb = (const float*)d_in[17];

    const size_t WS = (size_t)TT * DD * DD;
    const size_t ES = (size_t)HH * RR * DHh * DHh;
    const int TL_GRID = (NN + 63) / 64;
    const int NODE_GRID = (NN + 7) / 8;
    const int INIT_GRID = (NN * DD / 4 + 255) / 256;

    for (int l = 0; l < LLn; ++l) {
        int in_sel = (l == 0) ? 0 : 2;
        int ln_out = (l == 0) ? 0 : 1;
        init_kernel<<<INIT_GRID, 256>>>();
        typed_linear_kernel<<<TL_GRID, 256>>>(h, in_sel, ntyp,
                                              Wk + l * WS, Wq + l * WS, Wv + l * WS, 3);
        edge_fused_kernel<<<EDGE_GRID, 256>>>(src, dst, etyp,
                                              Watt + l * ES, Wmsg + l * ES,
                                              pri + l * HH * RR);
        typed_linear_kernel<<<TL_GRID, 256>>>(h, 1, ntyp,
                                              Wa + l * WS, Wa + l * WS, Wa + l * WS, 1);
        fuse_ln_kernel<<<NODE_GRID, 256>>>(h, in_sel, ntyp, skip + l * TT,
                                           lng + l * DD, lnb + l * DD, ln_out);
    }
    final_kernel<<<NODE_GRID, 256>>>(aggw, aggg, aggb, (float*)d_out);
}